// round 14
// baseline (speedup 1.0000x reference)
#include <cuda_runtime.h>
#include <cuda_fp16.h>
#include <cstdint>

// ---------------------------------------------------------------------------
// KAN-Mixer fused kernel (round 8): fp16 mma.sync m16n8k16, fp32 accumulate.
// BARRIER-FREE main loops: A fragments generated in registers by the consuming
// warp (2-ex2 paired-basis trick), B fragments loaded per-warp via __ldg from
// fragment-ordered weight blobs (L2-resident). No As/Bs smem, no cp.async,
// 3 __syncthreads total. 2 CTAs/SM.
// ---------------------------------------------------------------------------

#define PP   196
#define CC   768
#define HSZ  384

#define NT1  48            // n8 tiles layer1
#define NC1  56            // chunks of 32 k
#define NT2  25            // n8 tiles layer2 (200 = 196 padded to 8)
#define NC2  108

#define MTILE 64
#define NTH  256
#define L2E  1.4426950408889634f

#define W1ELEMS (112u * 48u * 64u)     // 344064 uints
#define W2ELEMS (216u * 25u * 64u)     // 345600 uints

// fragment-ordered packed fp16 weights (uint = half2):
// index = (ks16*NT + nt)*64 + lane*2 + r ; half2 = {W[n][k], W[n][k+1]},
// n = nt*8 + lane/4, k = ks16*16 + r*8 + (lane%4)*2
__device__ unsigned g_W1[W1ELEMS];   // 1.31 MB
__device__ unsigned g_W2[W2ELEMS];   // 1.32 MB

// ----------------------------- helpers --------------------------------------
static __device__ __forceinline__ float ex2f(float z) {
    float r; asm("ex2.approx.ftz.f32 %0, %1;" : "=f"(r) : "f"(z)); return r;
}
static __device__ __forceinline__ float rcpf(float z) {
    float r; asm("rcp.approx.ftz.f32 %0, %1;" : "=f"(r) : "f"(z)); return r;
}
static __device__ __forceinline__ float silu_feat(float v) {
    float z = fminf(fmaxf(-v * L2E, -126.0f), 126.0f);
    return v * rcpf(1.0f + ex2f(z));
}
static __device__ __forceinline__ unsigned h2pack(float a, float b) {
    __half2 h = __floats2half2_rn(a, b);
    return *reinterpret_cast<unsigned*>(&h);
}
static __device__ __forceinline__ void mma16(float* d, const uint4& A, const uint2& B) {
    asm volatile(
        "mma.sync.aligned.m16n8k16.row.col.f32.f16.f16.f32 "
        "{%0,%1,%2,%3}, {%4,%5,%6,%7}, {%8,%9}, {%0,%1,%2,%3};"
        : "+f"(d[0]), "+f"(d[1]), "+f"(d[2]), "+f"(d[3])
        : "r"(A.x), "r"(A.y), "r"(A.z), "r"(A.w), "r"(B.x), "r"(B.y));
}

// ------------------------- fused weight prep --------------------------------
__global__ void prep(const float* __restrict__ sw1, const float* __restrict__ bw1,
                     const float* __restrict__ sw2, const float* __restrict__ bw2) {
    unsigned gi = blockIdx.x * blockDim.x + threadIdx.x;
    if (gi < W1ELEMS) {
        unsigned idx = gi;
        unsigned r = idx & 1, lane = (idx >> 1) & 31;
        unsigned nt = (idx >> 6) % 48, ks = (idx >> 6) / 48;
        unsigned n = nt * 8 + (lane >> 2);
        unsigned k = ks * 16 + r * 8 + (lane & 3) * 2;
        float v0 = 0.0f, v1 = 0.0f;
        if (k < 1568)       v0 = sw1[n * 1568 + k];
        else if (k < 1764)  v0 = bw1[n * 196 + (k - 1568)];
        unsigned k1 = k + 1;
        if (k1 < 1568)      v1 = sw1[n * 1568 + k1];
        else if (k1 < 1764) v1 = bw1[n * 196 + (k1 - 1568)];
        g_W1[idx] = h2pack(v0, v1);
    } else if (gi < W1ELEMS + W2ELEMS) {
        unsigned idx = gi - W1ELEMS;
        unsigned r = idx & 1, lane = (idx >> 1) & 31;
        unsigned nt = (idx >> 6) % 25, ks = (idx >> 6) / 25;
        unsigned n = nt * 8 + (lane >> 2);
        unsigned k = ks * 16 + r * 8 + (lane & 3) * 2;
        float v0 = 0.0f, v1 = 0.0f;
        if (n < PP) {
            if (k < 3072)       v0 = sw2[n * 3072 + k];
            else                v0 = bw2[n * 384 + (k - 3072)];
            unsigned k1 = k + 1;
            if (k1 < 3072)      v1 = sw2[n * 3072 + k1];
            else                v1 = bw2[n * 384 + (k1 - 3072)];
        }
        g_W2[idx] = h2pack(v0, v1);
    }
}

// ------------------------------ main kernel ---------------------------------
// smem (float units):
//   [0,384)      b1s
//   [384,608)    b2s
//   [640,13184)  region0: xs fp32 [196][64] (L1) / hs fp16 [64][392] (L2)
#define SM_B1   0
#define SM_B2   384
#define SM_R0   640
#define SM_TOTF 13184
#define HST     392        // h stride in halfs

__global__ void __launch_bounds__(NTH, 2)
kan_main(const float* __restrict__ x, const float* __restrict__ b1,
         const float* __restrict__ b2, float* __restrict__ out) {
    extern __shared__ float smem[];
    float*  b1s = smem + SM_B1;
    float*  b2s = smem + SM_B2;
    float*  xs  = smem + SM_R0;                              // fp32 [196][64]
    __half* hs  = reinterpret_cast<__half*>(smem + SM_R0);   // fp16 [64][392]

    const int tid = threadIdx.x;
    const int w = tid >> 5, lane = tid & 31;
    const int mw = w & 1;           // row half
    const int nG = w >> 1;          // col group 0..3
    const int g = lane >> 2, c4 = lane & 3;
    // L2 n-tile assignment: 25 tiles split 7/6/6/6 over nG
    const int nt2_base = (nG == 0) ? 0 : (1 + 6 * nG);   // 0,7,13,19
    const int nt2_cnt  = (nG == 0) ? 7 : 6;

    // per-thread basis constants: this thread's k positions always have
    // q in {2c4, 2c4+1}
    const float C0 = 3.5f - 2.0f * (float)c4;   // d = x*3.5 + (3.5 - q0)

    const int m0 = blockIdx.x * MTILE;
    const int b  = m0 / CC;
    const int c0 = m0 % CC;

    const uint2* __restrict__ W1p = reinterpret_cast<const uint2*>(g_W1);
    const uint2* __restrict__ W2p = reinterpret_cast<const uint2*>(g_W2);

    // paired RBF features for (q0, q0+1) from one value: 2 ex2, ~5 flops
    auto bpair = [&](float v) -> unsigned {
        float d  = fmaf(v, 3.5f, C0);
        float z0 = d * (d * (-L2E));                       // -(d^2) log2e
        float z1 = fmaf(d, 2.0f * L2E, z0) - L2E;          // -((d-1)^2) log2e
        return h2pack(ex2f(z0), ex2f(z1));
    };

    // ---- load x slab + biases ----
    {
        const float4* xg = reinterpret_cast<const float4*>(x + (size_t)b * PP * CC + c0);
        float4* xs4 = reinterpret_cast<float4*>(xs);
        for (int i = tid; i < PP * 16; i += NTH) {
            int p = i >> 4, r4 = i & 15;
            xs4[p * 16 + r4] = xg[p * (CC / 4) + r4];
        }
        for (int i = tid; i < HSZ; i += NTH) b1s[i] = b1[i];
        if (tid < 200) b2s[tid] = (tid < PP) ? b2[tid] : 0.0f;
    }
    __syncthreads();

    // ============================ layer 1 ============================
    {
        float acc[2][12][4] = {};

        for (int kc = 0; kc < NC1; ++kc) {
#pragma unroll
            for (int ks = 0; ks < 2; ++ks) {
                const uint2* Wp = W1p + ((size_t)(kc * 2 + ks) * NT1 + nG * 12) * 32 + lane;
                uint2 B0[4], B1[4], B2[4];
#pragma unroll
                for (int j = 0; j < 4; ++j) B0[j] = __ldg(Wp + j * 32);

                // generate this warp's A fragments in registers
                uint4 A[2];
                if (kc < 49) {     // pure basis region
                    const int p0 = 4 * kc + 2 * ks;
#pragma unroll
                    for (int mi = 0; mi < 2; ++mi) {
                        const int Rl = mw * 32 + mi * 16 + g;
                        A[mi].x = bpair(xs[p0 * 64 + Rl]);
                        A[mi].y = bpair(xs[p0 * 64 + Rl + 8]);
                        A[mi].z = bpair(xs[(p0 + 1) * 64 + Rl]);
                        A[mi].w = bpair(xs[(p0 + 1) * 64 + Rl + 8]);
                    }
                } else {           // silu / pad region
                    const int kb = 32 * kc + 16 * ks + 2 * c4;
                    const int pa = kb - 1568, pb = pa + 1, pc = pa + 8, pd = pa + 9;
#pragma unroll
                    for (int mi = 0; mi < 2; ++mi) {
                        const int Rl = mw * 32 + mi * 16 + g, Rh = Rl + 8;
                        float fa0 = (pa < PP) ? silu_feat(xs[pa * 64 + Rl]) : 0.0f;
                        float fb0 = (pb < PP) ? silu_feat(xs[pb * 64 + Rl]) : 0.0f;
                        float fa1 = (pa < PP) ? silu_feat(xs[pa * 64 + Rh]) : 0.0f;
                        float fb1 = (pb < PP) ? silu_feat(xs[pb * 64 + Rh]) : 0.0f;
                        float fc0 = (pc < PP) ? silu_feat(xs[pc * 64 + Rl]) : 0.0f;
                        float fd0 = (pd < PP) ? silu_feat(xs[pd * 64 + Rl]) : 0.0f;
                        float fc1 = (pc < PP) ? silu_feat(xs[pc * 64 + Rh]) : 0.0f;
                        float fd1 = (pd < PP) ? silu_feat(xs[pd * 64 + Rh]) : 0.0f;
                        A[mi].x = h2pack(fa0, fb0);
                        A[mi].y = h2pack(fa1, fb1);
                        A[mi].z = h2pack(fc0, fd0);
                        A[mi].w = h2pack(fc1, fd1);
                    }
                }

#pragma unroll
                for (int j = 0; j < 4; ++j) B1[j] = __ldg(Wp + (4 + j) * 32);
#pragma unroll
                for (int j = 0; j < 4; ++j) {
                    mma16(acc[0][j], A[0], B0[j]);
                    mma16(acc[1][j], A[1], B0[j]);
                }
#pragma unroll
                for (int j = 0; j < 4; ++j) B2[j] = __ldg(Wp + (8 + j) * 32);
#pragma unroll
                for (int j = 0; j < 4; ++j) {
                    mma16(acc[0][4 + j], A[0], B1[j]);
                    mma16(acc[1][4 + j], A[1], B1[j]);
                }
#pragma unroll
                for (int j = 0; j < 4; ++j) {
                    mma16(acc[0][8 + j], A[0], B2[j]);
                    mma16(acc[1][8 + j], A[1], B2[j]);
                }
            }
        }

        __syncthreads();   // all warps done reading xs before hs overwrite

        // ---- h epilogue: hs[row][col] = fp16(acc + b1[col]) ----
#pragma unroll
        for (int mi = 0; mi < 2; ++mi)
#pragma unroll
            for (int nti = 0; nti < 12; ++nti)
#pragma unroll
                for (int ci = 0; ci < 4; ++ci) {
                    int row = mw * 32 + mi * 16 + g + 8 * (ci >> 1);
                    int col = nG * 96 + nti * 8 + 2 * c4 + (ci & 1);
                    hs[row * HST + col] = __float2half(acc[mi][nti][ci] + b1s[col]);
                }
    }
    __syncthreads();       // hs visible to all

    // ============================ layer 2 ============================
    {
        float acc[2][7][4] = {};

        for (int kc = 0; kc < NC2; ++kc) {
#pragma unroll
            for (int ks = 0; ks < 2; ++ks) {
                const uint2* Wp = W2p + ((size_t)(kc * 2 + ks) * NT2 + nt2_base) * 32 + lane;
                uint2 B0[4], B1[3];
#pragma unroll
                for (int j = 0; j < 4; ++j) B0[j] = __ldg(Wp + j * 32);

                uint4 A[2];
                if (kc < 96) {     // basis over h
                    const int j0 = 4 * kc + 2 * ks;
#pragma unroll
                    for (int mi = 0; mi < 2; ++mi) {
                        const int Rl = mw * 32 + mi * 16 + g, Rh = Rl + 8;
                        A[mi].x = bpair(__half2float(hs[Rl * HST + j0]));
                        A[mi].y = bpair(__half2float(hs[Rh * HST + j0]));
                        A[mi].z = bpair(__half2float(hs[Rl * HST + j0 + 1]));
                        A[mi].w = bpair(__half2float(hs[Rh * HST + j0 + 1]));
                    }
                } else {           // silu over h, k in [3072, 3456)
                    const int ja = 32 * kc + 16 * ks + 2 * c4 - 3072;
#pragma unroll
                    for (int mi = 0; mi < 2; ++mi) {
                        const int Rl = mw * 32 + mi * 16 + g, Rh = Rl + 8;
                        A[mi].x = h2pack(silu_feat(__half2float(hs[Rl * HST + ja])),
                                         silu_feat(__half2float(hs[Rl * HST + ja + 1])));
                        A[mi].y = h2pack(silu_feat(__half2float(hs[Rh * HST + ja])),
                                         silu_feat(__half2float(hs[Rh * HST + ja + 1])));
                        A[mi].z = h2pack(silu_feat(__half2float(hs[Rl * HST + ja + 8])),
                                         silu_feat(__half2float(hs[Rl * HST + ja + 9])));
                        A[mi].w = h2pack(silu_feat(__half2float(hs[Rh * HST + ja + 8])),
                                         silu_feat(__half2float(hs[Rh * HST + ja + 9])));
                    }
                }

#pragma unroll
                for (int j = 0; j < 3; ++j) {
                    int jj = (4 + j < nt2_cnt) ? (4 + j) : (nt2_cnt - 1);  // clamped (in-bounds)
                    B1[j] = __ldg(Wp + jj * 32);
                }
#pragma unroll
                for (int j = 0; j < 4; ++j) {
                    mma16(acc[0][j], A[0], B0[j]);
                    mma16(acc[1][j], A[1], B0[j]);
                }
#pragma unroll
                for (int j = 0; j < 3; ++j) {
                    if (4 + j < nt2_cnt) {
                        mma16(acc[0][4 + j], A[0], B1[j]);
                        mma16(acc[1][4 + j], A[1], B1[j]);
                    }
                }
            }
        }

        // ---- epilogue: out = acc + b2[p] + x (x re-read from gmem) ----
#pragma unroll
        for (int mi = 0; mi < 2; ++mi)
#pragma unroll
            for (int nti = 0; nti < 7; ++nti) {
                if (nti < nt2_cnt) {
#pragma unroll
                    for (int ci = 0; ci < 4; ++ci) {
                        int row = mw * 32 + mi * 16 + g + 8 * (ci >> 1);
                        int p   = (nt2_base + nti) * 8 + 2 * c4 + (ci & 1);
                        if (p < PP) {
                            size_t ga = ((size_t)b * PP + p) * CC + c0 + row;
                            out[ga] = acc[mi][nti][ci] + b2s[p] + x[ga];
                        }
                    }
                }
            }
    }
}

// ------------------------------ launcher ------------------------------------
extern "C" void kernel_launch(void* const* d_in, const int* in_sizes, int n_in,
                              void* d_out, int out_size) {
    (void)in_sizes; (void)n_in; (void)out_size;
    const float* x  = (const float*)d_in[0];
    const float* s1 = (const float*)d_in[1];
    const float* w1 = (const float*)d_in[2];
    const float* b1 = (const float*)d_in[3];
    const float* s2 = (const float*)d_in[4];
    const float* w2 = (const float*)d_in[5];
    const float* b2 = (const float*)d_in[6];
    float* out = (float*)d_out;

    prep<<<(W1ELEMS + W2ELEMS + 255) / 256, 256>>>(s1, w1, s2, w2);

    const int smemBytes = SM_TOTF * 4;   // 52,736 B -> 2 CTAs/SM (reg-bound)
    cudaFuncSetAttribute(kan_main, cudaFuncAttributeMaxDynamicSharedMemorySize, smemBytes);
    kan_main<<<(64 * CC) / MTILE, NTH, smemBytes>>>(x, b1, b2, out);
}